// round 7
// baseline (speedup 1.0000x reference)
#include <cuda_runtime.h>
#include <cstdint>

// ---------------------------------------------------------------------------
// EnrichAttention: x1/x2 projections -> scores -> softmax(dim=1) -> ctx ->
// concat -> GRU(512 steps). All fp32.
// ---------------------------------------------------------------------------

#define Bb   32
#define L1n  512
#define L2n  512
#define Hn   256
#define An   256

// scratch layout (floats)
#define OFF_T1 0
#define OFF_A1 4194304      // 16384*256
#define OFF_A2 8388608
#define OFF_M  12582912     // 32*512*512 = 8388608 floats
#define OFF_G  20971520     // 16384*512  = 8388608
#define OFF_XP 29360128     // 16384*768  = 12582912
#define OFF_H  41943040     // 2*32*256   = 16384
#define SCRATCH_FLOATS 41959424

__device__ float    g_scratch[SCRATCH_FLOATS];
__device__ unsigned g_bar;

// ---------------------------------------------------------------------------
// Generic 128x128 tile SGEMM, 256 threads, 8x8 microtile, K-tile 8.
// All dims assumed multiples of the tile sizes (true for this problem).
// EPI: 0=none, 1=relu, 2=mul by E[r*eN+c], 3=add bias E[c]
// TRANSB: true  -> B is [N,K] row-major (C = A * B^T)
//         false -> B is [K,N] row-major (C = A * B)
// blockIdx.z batches via sA/sB/sC strides; row indices are within-batch.
// ---------------------------------------------------------------------------
template<int EPI, bool TRANSB>
__global__ void __launch_bounds__(256) sgemm_kernel(
    const float* __restrict__ A, const float* __restrict__ B,
    float* __restrict__ C, int K, int lda, int ldb, int ldc,
    long long sA, long long sB, long long sC,
    const float* __restrict__ E, int eN)
{
    A += (size_t)blockIdx.z * sA;
    B += (size_t)blockIdx.z * sB;
    C += (size_t)blockIdx.z * sC;

    __shared__ float As[8][128];
    __shared__ float Bs[8][128];

    const int tid = threadIdx.x;
    const int tx = tid & 15, ty = tid >> 4;
    const int m0 = blockIdx.y * 128, n0 = blockIdx.x * 128;

    // loader indices (A and TRANSB-B): 128 rows x 8 k, one float4 per thread
    const int lr = tid >> 1;
    const int lk = (tid & 1) * 4;
    // NN-B loader: 8 k-rows x 128 cols
    const int bk = tid >> 5;
    const int bn = (tid & 31) * 4;

    float acc[8][8];
#pragma unroll
    for (int i = 0; i < 8; i++)
#pragma unroll
        for (int j = 0; j < 8; j++) acc[i][j] = 0.f;

    for (int k0 = 0; k0 < K; k0 += 8) {
        float4 av = *(const float4*)(A + (size_t)(m0 + lr) * lda + k0 + lk);
        float4 bv;
        if (TRANSB) bv = *(const float4*)(B + (size_t)(n0 + lr) * ldb + k0 + lk);
        else        bv = *(const float4*)(B + (size_t)(k0 + bk) * ldb + n0 + bn);

        __syncthreads();
        As[lk + 0][lr] = av.x; As[lk + 1][lr] = av.y;
        As[lk + 2][lr] = av.z; As[lk + 3][lr] = av.w;
        if (TRANSB) {
            Bs[lk + 0][lr] = bv.x; Bs[lk + 1][lr] = bv.y;
            Bs[lk + 2][lr] = bv.z; Bs[lk + 3][lr] = bv.w;
        } else {
            *(float4*)&Bs[bk][bn] = bv;
        }
        __syncthreads();

#pragma unroll
        for (int kk = 0; kk < 8; kk++) {
            float a[8], b[8];
            *(float4*)&a[0] = *(const float4*)&As[kk][ty * 8];
            *(float4*)&a[4] = *(const float4*)&As[kk][ty * 8 + 4];
            *(float4*)&b[0] = *(const float4*)&Bs[kk][tx * 8];
            *(float4*)&b[4] = *(const float4*)&Bs[kk][tx * 8 + 4];
#pragma unroll
            for (int i = 0; i < 8; i++)
#pragma unroll
                for (int j = 0; j < 8; j++) acc[i][j] += a[i] * b[j];
        }
    }

#pragma unroll
    for (int i = 0; i < 8; i++) {
        const int r = m0 + ty * 8 + i;
        float* crow = C + (size_t)r * ldc + n0 + tx * 8;
        float v[8];
#pragma unroll
        for (int j = 0; j < 8; j++) {
            float x = acc[i][j];
            const int c = n0 + tx * 8 + j;
            if (EPI == 1) x = fmaxf(x, 0.f);
            else if (EPI == 2) x *= E[(size_t)r * eN + c];
            else if (EPI == 3) x += E[c];
            v[j] = x;
        }
        *(float4*)crow       = make_float4(v[0], v[1], v[2], v[3]);
        *(float4*)(crow + 4) = make_float4(v[4], v[5], v[6], v[7]);
    }
}

// ---------------------------------------------------------------------------
// Softmax over dim=1 (the i axis) of M[32][512][512]. One thread per (b, j).
// ---------------------------------------------------------------------------
__global__ void softmax_dim1_kernel(float* __restrict__ Mm)
{
    const int idx = blockIdx.x * 256 + threadIdx.x;   // 0..16383
    const int b = idx >> 9, c = idx & 511;
    float* p = Mm + (size_t)b * (512 * 512) + c;

    float mx = -1e30f, s = 0.f;
    for (int i = 0; i < 512; i++) {
        const float v = p[(size_t)i * 512];
        const float nm = fmaxf(mx, v);
        s = s * __expf(mx - nm) + __expf(v - nm);
        mx = nm;
    }
    const float inv = 1.f / s;
    for (int i = 0; i < 512; i++) {
        const float v = p[(size_t)i * 512];
        p[(size_t)i * 512] = __expf(v - mx) * inv;
    }
}

// Copy x1 into the left half of g[16384][512]
__global__ void concat_copy_kernel(const float* __restrict__ x1, float* __restrict__ g)
{
    const int idx = blockIdx.x * 256 + threadIdx.x;   // 0..1048575
    const int m = idx >> 6;
    const int c4 = (idx & 63) << 2;
    *(float4*)&g[(size_t)m * 512 + c4] = *(const float4*)&x1[(size_t)m * 256 + c4];
}

// ---------------------------------------------------------------------------
// Persistent GRU: 128 CTAs x 256 threads, each CTA owns 2 hidden columns.
// Grid barrier per step (release/acquire + ping-pong h buffers in GMEM/L2).
// ---------------------------------------------------------------------------
__device__ __forceinline__ unsigned ld_acq(const unsigned* p) {
    unsigned v;
    asm volatile("ld.acquire.gpu.global.u32 %0, [%1];" : "=r"(v) : "l"(p) : "memory");
    return v;
}
__device__ __forceinline__ void red_rel(unsigned* p) {
    asm volatile("red.release.gpu.global.add.u32 [%0], 1;" :: "l"(p) : "memory");
}
__device__ __forceinline__ void grid_bar(unsigned* bar, unsigned& epoch, int tid) {
    __syncthreads();
    if (tid == 0) {
        red_rel(bar);
        epoch += 128;
        while (ld_acq(bar) < epoch) __nanosleep(64);
    }
    __syncthreads();
}

__global__ void __launch_bounds__(256, 1) gru_kernel(
    const float* __restrict__ xp,    // [32*512][768] : x-projection incl. bih
    const float* __restrict__ whh,   // [768][256]
    const float* __restrict__ bhh,   // [768]
    float* __restrict__ hbuf,        // [2][32*256] ping-pong
    unsigned* bar,
    float* __restrict__ out)         // [32*512][256]
{
    __shared__ float wpack[2][256][4];   // [h_local][k][{r,z,n,pad}]
    __shared__ float hsT[256][33];       // [k][b], padded
    __shared__ float part[2][3][4][32];  // [h_local][gate][kq][b]
    __shared__ float bhs[2][3];

    const int tid = threadIdx.x;
    const int cta = blockIdx.x;
    const int h0 = cta * 2;

    for (int idx = tid; idx < 1536; idx += 256) {
        const int k = idx & 255, rem = idx >> 8;     // rem 0..5
        const int hl = rem & 1, gg = rem >> 1;
        wpack[hl][k][gg] = whh[(size_t)(gg * 256 + h0 + hl) * 256 + k];
    }
    if (tid < 6) {
        const int hl = tid & 1, gg = tid >> 1;
        bhs[hl][gg] = bhh[gg * 256 + h0 + hl];
    }
    // zero h buffer 0 cooperatively across the grid
    if (tid < 64) hbuf[cta * 64 + tid] = 0.f;
    __threadfence();

    unsigned epoch = 0;
    grid_bar(bar, epoch, tid);

    const int b  = tid & 31;
    const int w  = tid >> 5;
    const int hl = w & 1;
    const int kq = w >> 1;           // 0..3 (k-slice of 64)
    const int fhl = tid >> 5;        // for finalizers (tid < 64)

    for (int t = 0; t < 512; t++) {
        const float* hcur = hbuf + (size_t)(t & 1) * 8192;
        float*       hnxt = hbuf + (size_t)((t + 1) & 1) * 8192;

        // stage h (transposed) from L2; __ldcg avoids stale L1
#pragma unroll
        for (int rr = 0; rr < 32; rr++)
            hsT[tid][rr] = __ldcg(&hcur[rr * 256 + tid]);

        float xr = 0.f, xz = 0.f, xn = 0.f;
        if (tid < 64) {
            const float* xpb = xp + ((size_t)b * 512 + t) * 768 + h0 + fhl;
            xr = __ldg(xpb);
            xz = __ldg(xpb + 256);
            xn = __ldg(xpb + 512);
        }
        __syncthreads();

        // partial dots: 3 gates x 64 k per thread
        float ar = 0.f, az = 0.f, an = 0.f;
        const int kb = kq * 64;
#pragma unroll 16
        for (int kk = 0; kk < 64; kk++) {
            const int k = kb + kk;
            const float hv = hsT[k][b];
            const float4 wv = *(const float4*)&wpack[hl][k][0];
            ar = fmaf(hv, wv.x, ar);
            az = fmaf(hv, wv.y, az);
            an = fmaf(hv, wv.z, an);
        }
        part[hl][0][kq][b] = ar;
        part[hl][1][kq][b] = az;
        part[hl][2][kq][b] = an;
        __syncthreads();

        if (tid < 64) {
            const float hr = part[fhl][0][0][b] + part[fhl][0][1][b] +
                             part[fhl][0][2][b] + part[fhl][0][3][b] + bhs[fhl][0];
            const float hz = part[fhl][1][0][b] + part[fhl][1][1][b] +
                             part[fhl][1][2][b] + part[fhl][1][3][b] + bhs[fhl][1];
            const float hn = part[fhl][2][0][b] + part[fhl][2][1][b] +
                             part[fhl][2][2][b] + part[fhl][2][3][b] + bhs[fhl][2];
            const float rg = 1.f / (1.f + __expf(-(xr + hr)));
            const float zg = 1.f / (1.f + __expf(-(xz + hz)));
            const float ng = tanhf(xn + rg * hn);
            const float hp = hsT[h0 + fhl][b];
            const float hnew = (1.f - zg) * ng + zg * hp;
            hnxt[b * 256 + h0 + fhl] = hnew;
            out[((size_t)b * 512 + t) * 256 + h0 + fhl] = hnew;
            __threadfence();   // make hnew visible at GPU scope before arrival
        }
        grid_bar(bar, epoch, tid);
    }
}

// ---------------------------------------------------------------------------
extern "C" void kernel_launch(void* const* d_in, const int* in_sizes, int n_in,
                              void* d_out, int out_size)
{
    const float* x1  = (const float*)d_in[0];
    const float* x2  = (const float*)d_in[1];
    const float* w1  = (const float*)d_in[2];
    const float* w2  = (const float*)d_in[3];
    const float* Dm  = (const float*)d_in[4];
    const float* Wm  = (const float*)d_in[5];
    const float* wih = (const float*)d_in[6];
    const float* whh = (const float*)d_in[7];
    const float* bih = (const float*)d_in[8];
    const float* bhh = (const float*)d_in[9];
    float* out = (float*)d_out;

    float* scratch = nullptr;
    unsigned* bar = nullptr;
    cudaGetSymbolAddress((void**)&scratch, g_scratch);
    cudaGetSymbolAddress((void**)&bar, g_bar);
    cudaMemsetAsync(bar, 0, sizeof(unsigned));

    float* T1 = scratch + OFF_T1;
    float* A1 = scratch + OFF_A1;
    float* A2 = scratch + OFF_A2;
    float* MM = scratch + OFF_M;
    float* GG = scratch + OFF_G;
    float* XP = scratch + OFF_XP;
    float* HH = scratch + OFF_H;

    const dim3 blk(256);

    // t1 = relu(x1 @ w1^T)   [16384,256]
    sgemm_kernel<1, true><<<dim3(2, 128, 1), blk>>>(
        x1, w1, T1, 256, 256, 256, 256, 0, 0, 0, nullptr, 0);
    // a2 = relu(x2 @ w2^T)
    sgemm_kernel<1, true><<<dim3(2, 128, 1), blk>>>(
        x2, w2, A2, 256, 256, 256, 256, 0, 0, 0, nullptr, 0);
    // a1 = t1 @ D
    sgemm_kernel<0, false><<<dim3(2, 128, 1), blk>>>(
        T1, Dm, A1, 256, 256, 256, 256, 0, 0, 0, nullptr, 0);
    // M[b] = (a1[b] @ a2[b]^T) * W      [32][512][512]
    sgemm_kernel<2, true><<<dim3(4, 4, 32), blk>>>(
        A1, A2, MM, 256, 256, 256, 512,
        (long long)512 * 256, (long long)512 * 256, (long long)512 * 512, Wm, 512);
    // softmax over dim=1 (i axis)
    softmax_dim1_kernel<<<64, 256>>>(MM);
    // g left half <- x1
    concat_copy_kernel<<<4096, 256>>>(x1, GG);
    // ctx[b] = M[b] @ x2[b]  -> g right half (ldc=512, col offset 256)
    sgemm_kernel<0, false><<<dim3(2, 4, 32), blk>>>(
        MM, x2, GG + 256, 512, 512, 256, 512,
        (long long)512 * 512, (long long)512 * 256, (long long)512 * 512, nullptr, 0);
    // xp = g @ wih^T + bih   [16384][768]
    sgemm_kernel<3, true><<<dim3(6, 128, 1), blk>>>(
        GG, wih, XP, 512, 512, 512, 768, 0, 0, 0, bih, 0);
    // GRU recurrence (persistent, grid-barriered)
    gru_kernel<<<128, 256>>>(XP, whh, bhh, HH, bar, out);
}